// round 8
// baseline (speedup 1.0000x reference)
#include <cuda_runtime.h>
#include <cstdint>

typedef unsigned long long ull;

#define B_  64
#define L_  1024
#define LI_ 256
#define A_  1024
#define H_  512

// ---------------- scratch (static device globals; no allocations) ----------
__device__ float g_gp1[4*8*B_*A_];      // gemm1 split-k partials [mat][kc][b][a]
__device__ float g_gp2[2*8*B_*A_];      // gemm2 split-k partials
__device__ float g_df [4*B_*A_];        // df, dfi, d3, d4
__device__ float g_e      [B_*L_];
__device__ float g_e_img  [B_*LI_];
__device__ float g_attn   [B_*L_];
__device__ float g_attn_img[B_*LI_];
__device__ float g_ctxp_t[B_*32*A_];    // ctx split-L partials (32 chunks)
__device__ float g_ctxp_i[B_*8*A_];     // (8 chunks)
__device__ float g_ctx_t[B_*A_];
__device__ float g_ctx_i[B_*A_];

// ---------------- packed f32x2 helpers -------------------------------------
__device__ __forceinline__ ull pk2(float lo, float hi) {
    ull d; asm("mov.b64 %0,{%1,%2};" : "=l"(d) : "f"(lo), "f"(hi)); return d;
}
__device__ __forceinline__ void upk2(ull d, float& lo, float& hi) {
    asm("mov.b64 {%0,%1},%2;" : "=f"(lo), "=f"(hi) : "l"(d));
}
__device__ __forceinline__ ull mul2(ull a, ull b) {
    ull d; asm("mul.rn.f32x2 %0,%1,%2;" : "=l"(d) : "l"(a), "l"(b)); return d;
}
__device__ __forceinline__ ull add2(ull a, ull b) {
    ull d; asm("add.rn.f32x2 %0,%1,%2;" : "=l"(d) : "l"(a), "l"(b)); return d;
}
__device__ __forceinline__ ull fma2(ull a, ull b, ull c) {
    ull d; asm("fma.rn.f32x2 %0,%1,%2,%3;" : "=l"(d) : "l"(a), "l"(b), "l"(c)); return d;
}
__device__ __forceinline__ ull cst2(float c) { return pk2(c, c); }

// clamp both halves to [-4.9, 4.9] via FMNMX (alu pipe, not fma pipe)
__device__ __forceinline__ ull clamp2(ull x) {
    float lo, hi; upk2(x, lo, hi);
    lo = fminf(fmaxf(lo, -4.9f), 4.9f);
    hi = fminf(fmaxf(hi, -4.9f), 4.9f);
    return pk2(lo, hi);
}

// FMA-only packed tanh: order-7 Lambert continued fraction, valid on [-4.9,4.9]
// (inputs must be pre-clamped). Max abs err ~8.5e-5. 13 f32x2 ops.
__device__ __forceinline__ ull tanh2(ull x) {
    ull x2 = mul2(x, x);
    ull p = fma2(x2, cst2(7.4000296e-6f), cst2(2.7972028e-3f));
    p = fma2(x2, p, cst2(0.12820513f));
    p = fma2(x2, p, cst2(1.0f));
    p = mul2(p, x);
    ull q = fma2(x2, cst2(2.0718275e-4f), cst2(0.023310023f));
    q = fma2(x2, q, cst2(0.46153846f));
    q = fma2(x2, q, cst2(1.0f));
    // reciprocal of q (q >= 1, positive): bit-hack + 2 Newton, no MUFU
    float ql, qh; upk2(q, ql, qh);
    float rl = __uint_as_float(0x7EF311C3u - __float_as_uint(ql));
    float rh = __uint_as_float(0x7EF311C3u - __float_as_uint(qh));
    ull r = pk2(rl, rh);
    ull nq = q ^ 0x8000000080000000ULL;
    ull two = cst2(2.0f);
    r = mul2(r, fma2(nq, r, two));
    r = mul2(r, fma2(nq, r, two));
    return mul2(p, r);
}

// ---------------- GEMM: split-K partial sums, f32x2 accumulators ----------
__global__ __launch_bounds__(256) void gemm_partial(
    const float* __restrict__ sa, const float* __restrict__ sb,
    const float* __restrict__ W0, const float* __restrict__ W1p,
    const float* __restrict__ W2p, const float* __restrict__ W3p,
    int mode)
{
    int z = blockIdx.z, kc = blockIdx.y;
    const float* W = (z == 0) ? W0 : (z == 1) ? W1p : (z == 2) ? W2p : W3p;

    __shared__ ulonglong2 dsh2[128 * 16];     // [k][bpair/2], 16B aligned
    ull* dsh = (ull*)dsh2;
    int tid = threadIdx.x;

    for (int i = tid; i < 128 * 32; i += 256) {
        int k = i >> 5, bp = i & 31;
        int kg = kc * 128 + k;
        int b0 = bp * 2, b1 = b0 + 1;
        float f0, f1;
        if (mode) {
            const float* s = z ? g_ctx_i : g_ctx_t;
            f0 = s[b0 * 1024 + kg];
            f1 = s[b1 * 1024 + kg];
        } else {
            if (kg < 512) { f0 = sa[b0 * 512 + kg];       f1 = sa[b1 * 512 + kg]; }
            else          { f0 = sb[b0 * 512 + kg - 512]; f1 = sb[b1 * 512 + kg - 512]; }
        }
        dsh[i] = pk2(f0, f1);
    }
    __syncthreads();

    int a = blockIdx.x * 256 + tid;
    const float* Wc = W + (size_t)(kc * 128) * 1024 + a;

    ull acc[32];
#pragma unroll
    for (int i = 0; i < 32; i++) acc[i] = 0ULL;

    for (int k = 0; k < 128; k++) {
        float w = __ldcs(&Wc[(size_t)k * 1024]);
        ull w2 = pk2(w, w);
        const ulonglong2* dk = &dsh2[k * 16];
#pragma unroll
        for (int q = 0; q < 16; q++) {
            ulonglong2 d = dk[q];
            acc[2 * q]     = fma2(d.x, w2, acc[2 * q]);
            acc[2 * q + 1] = fma2(d.y, w2, acc[2 * q + 1]);
        }
    }

    float* gp = mode ? g_gp2 : g_gp1;
    float* op = gp + ((size_t)(z * 8 + kc) * 64) * 1024 + a;
#pragma unroll
    for (int bp = 0; bp < 32; bp++) {
        float lo, hi; upk2(acc[bp], lo, hi);
        op[(size_t)(2 * bp)     * 1024] = lo;
        op[(size_t)(2 * bp + 1) * 1024] = hi;
    }
}

// reduce gemm1 partials + bias -> g_df[mat][b][a]
__global__ __launch_bounds__(256) void gemm_reduce(
    const float* __restrict__ bias0, const float* __restrict__ bias1,
    const float* __restrict__ bias2, const float* __restrict__ bias3)
{
    int idx = blockIdx.x * 256 + threadIdx.x;    // 0..262143
    int mat = idx >> 16;
    int r   = idx & 65535;
    int a   = idx & 1023;
    const float* bias = (mat == 0) ? bias0 : (mat == 1) ? bias1 : (mat == 2) ? bias2 : bias3;
    float s = bias[a];
#pragma unroll
    for (int c = 0; c < 8; c++) s += g_gp1[((mat * 8 + c) << 16) + r];
    g_df[idx] = s;
}

// ---------------- energy: e[b,l] = sum_a v[a]*tanh(F[b,l,a]+df[b,a]+cov*wc[a])
// one warp per 4 consecutive rows; cross-row software pipeline:
// while computing row r's tanh chain, issue row r+1's 8 LDG.128.
__global__ __launch_bounds__(256, 4) void energy_kernel(
    const float* __restrict__ F, const float* __restrict__ cov,
    const float* __restrict__ v, const float* __restrict__ wcp,
    const int* __restrict__ covset, int mat, int Lr, int img)
{
    __shared__ ulonglong2 sh_df[256], sh_wc[256], sh_v[256];
    int rgpb = Lr >> 5;                        // 32-row groups per batch
    int b  = blockIdx.x / rgpb;
    int l0 = (blockIdx.x % rgpb) * 32 + (threadIdx.x >> 5) * 4;
    int lane = threadIdx.x & 31;

    const float* dfm = g_df + (size_t)mat * (B_ * A_) + (size_t)b * A_;
    const float4* dfr = (const float4*)dfm;
    const float4* wcr = (const float4*)wcp;
    const float4* vr  = (const float4*)v;
    {
        int i = threadIdx.x;
        float4 t = dfr[i]; sh_df[i].x = pk2(t.x, t.y); sh_df[i].y = pk2(t.z, t.w);
        t = wcr[i];        sh_wc[i].x = pk2(t.x, t.y); sh_wc[i].y = pk2(t.z, t.w);
        t = vr[i];         sh_v [i].x = pk2(t.x, t.y); sh_v [i].y = pk2(t.z, t.w);
    }
    __syncthreads();

    int cs = *covset;
    float* eo = img ? g_e_img : g_e;
    const float4* Fr = (const float4*)(F + ((size_t)b * Lr + l0) * A_);

    // warmup: front-batch row 0
    float4 f[8];
#pragma unroll
    for (int i = 0; i < 8; i++) f[i] = __ldcs(&Fr[i * 32 + lane]);

#pragma unroll 1
    for (int r = 0; r < 4; r++) {
        float c = cs ? cov[b * Lr + l0 + r] : 0.0f;
        ull c2 = pk2(c, c);
        const float4* Fn = Fr + (size_t)(r + 1) * 256;   // next row base
        bool more = (r < 3);

        ull acc0 = 0ULL, acc1 = 0ULL;
#pragma unroll
        for (int ch = 0; ch < 8; ch++) {
            float4 cur = f[ch];
            if (more) f[ch] = __ldcs(&Fn[ch * 32 + lane]);   // prefetch next row
            int j = ch * 32 + lane;
            ulonglong2 d = sh_df[j], w = sh_wc[j], vv = sh_v[j];
            ull x0 = clamp2(add2(pk2(cur.x, cur.y), fma2(c2, w.x, d.x)));
            ull x1 = clamp2(add2(pk2(cur.z, cur.w), fma2(c2, w.y, d.y)));
            acc0 = fma2(vv.x, tanh2(x0), acc0);
            acc1 = fma2(vv.y, tanh2(x1), acc1);
        }
        ull acc = add2(acc0, acc1);
        float s0, s1; upk2(acc, s0, s1);
        float s = s0 + s1;
#pragma unroll
        for (int o = 16; o > 0; o >>= 1) s += __shfl_xor_sync(0xffffffffu, s, o);
        if (lane == 0) eo[b * Lr + l0 + r] = s;
    }
}

// ---------------- softmax (+mask renorm for text) + coverage update --------
__global__ __launch_bounds__(256) void softmax_kernel(
    const float* __restrict__ mask, const float* __restrict__ cov,
    const int* __restrict__ covset, float* __restrict__ attn_out,
    float* __restrict__ cov_out, int Lr, int img)
{
    int b = blockIdx.x, tid = threadIdx.x;
    int n = Lr >> 8;                       // 4 text, 1 img
    const float* e = img ? g_e_img : g_e;
    float* attn_g  = img ? g_attn_img : g_attn;
    __shared__ float red[256];

    const float* er = e + b * Lr;
    float vals[4], ex[4], p[4];
    float m = -3.4e38f;
    for (int i = 0; i < n; i++) { vals[i] = er[tid + (i << 8)]; m = fmaxf(m, vals[i]); }
    red[tid] = m; __syncthreads();
    for (int s = 128; s > 0; s >>= 1) { if (tid < s) red[tid] = fmaxf(red[tid], red[tid + s]); __syncthreads(); }
    m = red[0]; __syncthreads();

    float sum = 0.0f;
    for (int i = 0; i < n; i++) { ex[i] = __expf(vals[i] - m); sum += ex[i]; }
    red[tid] = sum; __syncthreads();
    for (int s = 128; s > 0; s >>= 1) { if (tid < s) red[tid] += red[tid + s]; __syncthreads(); }
    float S = red[0]; __syncthreads();

    float sum2 = 0.0f;
    for (int i = 0; i < n; i++) {
        float mk = mask ? mask[b * Lr + tid + (i << 8)] : 1.0f;
        p[i] = ex[i] / S * mk; sum2 += p[i];
    }
    red[tid] = sum2; __syncthreads();
    for (int s = 128; s > 0; s >>= 1) { if (tid < s) red[tid] += red[tid + s]; __syncthreads(); }
    float S2 = red[0];

    int cs = *covset;
    for (int i = 0; i < n; i++) {
        int idx = b * Lr + tid + (i << 8);
        float at = p[i] / S2;
        attn_g[idx]  = at;
        attn_out[idx] = at;
        cov_out[idx] = cs ? (cov[idx] + at) : at;
    }
}

// ---------------- ctx = attn · enc_outputs (split-L, 32 rows/chunk) --------
// rolling depth-8 prefetch; __ldcs streaming loads; dual accumulator chains
__global__ __launch_bounds__(256, 4) void ctx_partial(
    const float* __restrict__ O, int Lr, int img)
{
    int b = blockIdx.x, ch = blockIdx.y;
    const float* attn = img ? g_attn_img : g_attn;
    float* part       = img ? g_ctxp_i   : g_ctxp_t;
    __shared__ float ash[32];
    int tid = threadIdx.x;
    if (tid < 32) ash[tid] = attn[b * Lr + ch * 32 + tid];
    __syncthreads();

    const float4* Ob = (const float4*)(O + ((size_t)b * Lr + (size_t)ch * 32) * A_);

    float4 buf[8];
#pragma unroll
    for (int i = 0; i < 8; i++) buf[i] = __ldcs(&Ob[(size_t)i * 256 + tid]);

    float4 acc0 = make_float4(0.f, 0.f, 0.f, 0.f);
    float4 acc1 = make_float4(0.f, 0.f, 0.f, 0.f);
#pragma unroll
    for (int l = 0; l < 32; l++) {
        float4 o = buf[l & 7];
        if (l < 24) buf[l & 7] = __ldcs(&Ob[(size_t)(l + 8) * 256 + tid]);
        float s = ash[l];
        if (l & 1) {
            acc1.x += s * o.x; acc1.y += s * o.y; acc1.z += s * o.z; acc1.w += s * o.w;
        } else {
            acc0.x += s * o.x; acc0.y += s * o.y; acc0.z += s * o.z; acc0.w += s * o.w;
        }
    }
    acc0.x += acc1.x; acc0.y += acc1.y; acc0.z += acc1.z; acc0.w += acc1.w;
    float4* pp = (float4*)(part + ((size_t)b * gridDim.y + ch) * A_);
    pp[tid] = acc0;
}

__global__ __launch_bounds__(256) void ctx_reduce(int CH, int img)
{
    int idx = blockIdx.x * 256 + threadIdx.x;   // 0..65535
    int b = idx >> 10, a = idx & 1023;
    const float* part = img ? g_ctxp_i : g_ctxp_t;
    float s = 0.0f;
    for (int c = 0; c < CH; c++) s += part[((size_t)b * CH + c) * 1024 + a];
    (img ? g_ctx_i : g_ctx_t)[idx] = s;
}

// ---------------- final: beta gating + ctx_mm -------------------------------
__global__ __launch_bounds__(256) void final_kernel(
    const float* __restrict__ v3, const float* __restrict__ v4,
    float* __restrict__ out)
{
    int idx = blockIdx.x * 256 + threadIdx.x;   // 0..65535
    int a = idx & 1023;
    float ca = g_df[2 * 65536 + idx];           // dec@W3 + b3
    float cb = g_df[3 * 65536 + idx];           // dec@W4 + b4
#pragma unroll
    for (int c = 0; c < 8; c++) {
        ca += g_gp2[(c << 16) + idx];           // + ctx_t @ WA
        cb += g_gp2[((8 + c) << 16) + idx];     // + ctx_i @ WB
    }
    float b1v = v3[a] * tanhf(ca);
    float b2v = v4[a] * tanhf(cb);
    out[idx] = b1v * g_ctx_t[idx] + b2v * g_ctx_i[idx];
}

// ---------------- launch ----------------------------------------------------
extern "C" void kernel_launch(void* const* d_in, const int* in_sizes, int n_in,
                              void* d_out, int out_size)
{
    const float* h0       = (const float*)d_in[0];
    const float* h1       = (const float*)d_in[1];
    const float* enc_out  = (const float*)d_in[2];
    const float* enc_feat = (const float*)d_in[3];
    const float* enc_mask = (const float*)d_in[4];
    const float* coverage = (const float*)d_in[5];
    const float* eio      = (const float*)d_in[6];
    const float* eif      = (const float*)d_in[7];
    const float* cov_img  = (const float*)d_in[9];
    const int*   covset   = (const int*)  d_in[10];
    const float* W1 = (const float*)d_in[11];
    const float* b1 = (const float*)d_in[12];
    const float* W2 = (const float*)d_in[13];
    const float* b2 = (const float*)d_in[14];
    const float* W3 = (const float*)d_in[15];
    const float* b3 = (const float*)d_in[16];
    const float* W4 = (const float*)d_in[17];
    const float* b4 = (const float*)d_in[18];
    const float* WA = (const float*)d_in[19];
    const float* WB = (const float*)d_in[20];
    const float* v1 = (const float*)d_in[21];
    const float* v2 = (const float*)d_in[22];
    const float* v3 = (const float*)d_in[23];
    const float* v4 = (const float*)d_in[24];
    const float* wc = (const float*)d_in[25];
    const float* wci= (const float*)d_in[26];

    float* out = (float*)d_out;
    // output layout: ctx_mm[65536] | attn[65536] | attn_img[16384] |
    //                coverage[65536] | coverage_img[16384]
    float* o_attn     = out + 65536;
    float* o_attn_img = out + 131072;
    float* o_cov      = out + 147456;
    float* o_cov_img  = out + 212992;

    // 1) dec@{W1..W4}+bias  (split-K)
    gemm_partial<<<dim3(4, 8, 4), 256>>>(h0, h1, W1, W2, W3, W4, 0);
    gemm_reduce<<<1024, 256>>>(b1, b2, b3, b4);

    // 2) attention energies (the big HBM passes; 32 rows/block, 4 rows/warp)
    energy_kernel<<<(B_ * L_)  / 32, 256>>>(enc_feat, coverage, v1, wc,  covset, 0, L_,  0);
    energy_kernel<<<(B_ * LI_) / 32, 256>>>(eif,      cov_img,  v2, wci, covset, 1, LI_, 1);

    // 3) softmax + mask-renorm (text) / softmax (img) + coverage update
    softmax_kernel<<<B_, 256>>>(enc_mask, coverage, covset, o_attn,     o_cov,     L_,  0);
    softmax_kernel<<<B_, 256>>>(nullptr,  cov_img,  covset, o_attn_img, o_cov_img, LI_, 1);

    // 4) contexts (big HBM passes, split-L 32 rows/chunk)
    ctx_partial<<<dim3(B_, 32), 256>>>(enc_out, L_,  0);
    ctx_partial<<<dim3(B_, 8),  256>>>(eio,     LI_, 1);
    ctx_reduce<<<256, 256>>>(32, 0);
    ctx_reduce<<<256, 256>>>(8,  1);

    // 5) ctx@{WA,WB} (split-K) + gated combine
    gemm_partial<<<dim3(4, 8, 2), 256>>>(nullptr, nullptr, WA, WB, WA, WB, 1);
    final_kernel<<<256, 256>>>(v3, v4, out);
}

// round 10
// speedup vs baseline: 1.0319x; 1.0319x over previous
#include <cuda_runtime.h>
#include <cstdint>

typedef unsigned long long ull;

#define B_  64
#define L_  1024
#define LI_ 256
#define A_  1024
#define H_  512

// ---------------- scratch (static device globals; no allocations) ----------
__device__ float g_gp1[4*8*B_*A_];      // gemm1 split-k partials [mat][kc][b][a]
__device__ float g_gp2[2*8*B_*A_];      // gemm2 split-k partials
__device__ float g_df [4*B_*A_];        // df, dfi, d3, d4
__device__ float g_e      [B_*L_];
__device__ float g_e_img  [B_*LI_];
__device__ float g_attn   [B_*L_];
__device__ float g_attn_img[B_*LI_];
__device__ float g_ctxp_t[B_*32*A_];    // ctx split-L partials (32 chunks)
__device__ float g_ctxp_i[B_*8*A_];     // (8 chunks)
__device__ float g_ctx_t[B_*A_];
__device__ float g_ctx_i[B_*A_];

// ---------------- packed f32x2 helpers -------------------------------------
__device__ __forceinline__ ull pk2(float lo, float hi) {
    ull d; asm("mov.b64 %0,{%1,%2};" : "=l"(d) : "f"(lo), "f"(hi)); return d;
}
__device__ __forceinline__ void upk2(ull d, float& lo, float& hi) {
    asm("mov.b64 {%0,%1},%2;" : "=f"(lo), "=f"(hi) : "l"(d));
}
__device__ __forceinline__ ull mul2(ull a, ull b) {
    ull d; asm("mul.rn.f32x2 %0,%1,%2;" : "=l"(d) : "l"(a), "l"(b)); return d;
}
__device__ __forceinline__ ull add2(ull a, ull b) {
    ull d; asm("add.rn.f32x2 %0,%1,%2;" : "=l"(d) : "l"(a), "l"(b)); return d;
}
__device__ __forceinline__ ull fma2(ull a, ull b, ull c) {
    ull d; asm("fma.rn.f32x2 %0,%1,%2,%3;" : "=l"(d) : "l"(a), "l"(b), "l"(c)); return d;
}
__device__ __forceinline__ ull cst2(float c) { return pk2(c, c); }

// clamp both halves to [-4.9, 4.9] via FMNMX (alu pipe, not fma pipe)
__device__ __forceinline__ ull clamp2(ull x) {
    float lo, hi; upk2(x, lo, hi);
    lo = fminf(fmaxf(lo, -4.9f), 4.9f);
    hi = fminf(fmaxf(hi, -4.9f), 4.9f);
    return pk2(lo, hi);
}

// FMA-only packed tanh: order-7 Lambert continued fraction, valid on [-4.9,4.9]
// (inputs must be pre-clamped). Max abs err ~8.5e-5. 13 f32x2 ops.
__device__ __forceinline__ ull tanh2(ull x) {
    ull x2 = mul2(x, x);
    ull p = fma2(x2, cst2(7.4000296e-6f), cst2(2.7972028e-3f));
    p = fma2(x2, p, cst2(0.12820513f));
    p = fma2(x2, p, cst2(1.0f));
    p = mul2(p, x);
    ull q = fma2(x2, cst2(2.0718275e-4f), cst2(0.023310023f));
    q = fma2(x2, q, cst2(0.46153846f));
    q = fma2(x2, q, cst2(1.0f));
    // reciprocal of q (q >= 1, positive): bit-hack + 2 Newton, no MUFU
    float ql, qh; upk2(q, ql, qh);
    float rl = __uint_as_float(0x7EF311C3u - __float_as_uint(ql));
    float rh = __uint_as_float(0x7EF311C3u - __float_as_uint(qh));
    ull r = pk2(rl, rh);
    ull nq = q ^ 0x8000000080000000ULL;
    ull two = cst2(2.0f);
    r = mul2(r, fma2(nq, r, two));
    r = mul2(r, fma2(nq, r, two));
    return mul2(p, r);
}

// ---------------- GEMM: split-K partial sums, f32x2 accumulators ----------
__global__ __launch_bounds__(256) void gemm_partial(
    const float* __restrict__ sa, const float* __restrict__ sb,
    const float* __restrict__ W0, const float* __restrict__ W1p,
    const float* __restrict__ W2p, const float* __restrict__ W3p,
    int mode)
{
    int z = blockIdx.z, kc = blockIdx.y;
    const float* W = (z == 0) ? W0 : (z == 1) ? W1p : (z == 2) ? W2p : W3p;

    __shared__ ulonglong2 dsh2[128 * 16];     // [k][bpair/2], 16B aligned
    ull* dsh = (ull*)dsh2;
    int tid = threadIdx.x;

    for (int i = tid; i < 128 * 32; i += 256) {
        int k = i >> 5, bp = i & 31;
        int kg = kc * 128 + k;
        int b0 = bp * 2, b1 = b0 + 1;
        float f0, f1;
        if (mode) {
            const float* s = z ? g_ctx_i : g_ctx_t;
            f0 = s[b0 * 1024 + kg];
            f1 = s[b1 * 1024 + kg];
        } else {
            if (kg < 512) { f0 = sa[b0 * 512 + kg];       f1 = sa[b1 * 512 + kg]; }
            else          { f0 = sb[b0 * 512 + kg - 512]; f1 = sb[b1 * 512 + kg - 512]; }
        }
        dsh[i] = pk2(f0, f1);
    }
    __syncthreads();

    int a = blockIdx.x * 256 + tid;
    const float* Wc = W + (size_t)(kc * 128) * 1024 + a;

    ull acc[32];
#pragma unroll
    for (int i = 0; i < 32; i++) acc[i] = 0ULL;

    for (int k = 0; k < 128; k++) {
        float w = __ldcs(&Wc[(size_t)k * 1024]);
        ull w2 = pk2(w, w);
        const ulonglong2* dk = &dsh2[k * 16];
#pragma unroll
        for (int q = 0; q < 16; q++) {
            ulonglong2 d = dk[q];
            acc[2 * q]     = fma2(d.x, w2, acc[2 * q]);
            acc[2 * q + 1] = fma2(d.y, w2, acc[2 * q + 1]);
        }
    }

    float* gp = mode ? g_gp2 : g_gp1;
    float* op = gp + ((size_t)(z * 8 + kc) * 64) * 1024 + a;
#pragma unroll
    for (int bp = 0; bp < 32; bp++) {
        float lo, hi; upk2(acc[bp], lo, hi);
        op[(size_t)(2 * bp)     * 1024] = lo;
        op[(size_t)(2 * bp + 1) * 1024] = hi;
    }
}

// reduce gemm1 partials + bias -> g_df[mat][b][a]
__global__ __launch_bounds__(256) void gemm_reduce(
    const float* __restrict__ bias0, const float* __restrict__ bias1,
    const float* __restrict__ bias2, const float* __restrict__ bias3)
{
    int idx = blockIdx.x * 256 + threadIdx.x;    // 0..262143
    int mat = idx >> 16;
    int r   = idx & 65535;
    int a   = idx & 1023;
    const float* bias = (mat == 0) ? bias0 : (mat == 1) ? bias1 : (mat == 2) ? bias2 : bias3;
    float s = bias[a];
#pragma unroll
    for (int c = 0; c < 8; c++) s += g_gp1[((mat * 8 + c) << 16) + r];
    g_df[idx] = s;
}

// ---------------- energy: e[b,l] = sum_a v[a]*tanh(F[b,l,a]+df[b,a]+cov*wc[a])
// chunk-outer / row-inner: one warp per 2 rows. Per chunk: 1x LDS of d/w/v
// (row-invariant), double-buffered LDGs, 4 independent tanh chains (ILP=4).
__global__ __launch_bounds__(256, 4) void energy_kernel(
    const float* __restrict__ F, const float* __restrict__ cov,
    const float* __restrict__ v, const float* __restrict__ wcp,
    const int* __restrict__ covset, int mat, int Lr, int img)
{
    __shared__ ulonglong2 sh_df[256], sh_wc[256], sh_v[256];
    int rgpb = Lr >> 4;                        // 16-row groups per batch
    int b  = blockIdx.x / rgpb;
    int l0 = (blockIdx.x % rgpb) * 16 + (threadIdx.x >> 5) * 2;
    int lane = threadIdx.x & 31;

    const float* dfm = g_df + (size_t)mat * (B_ * A_) + (size_t)b * A_;
    const float4* dfr = (const float4*)dfm;
    const float4* wcr = (const float4*)wcp;
    const float4* vr  = (const float4*)v;
    {
        int i = threadIdx.x;
        float4 t = dfr[i]; sh_df[i].x = pk2(t.x, t.y); sh_df[i].y = pk2(t.z, t.w);
        t = wcr[i];        sh_wc[i].x = pk2(t.x, t.y); sh_wc[i].y = pk2(t.z, t.w);
        t = vr[i];         sh_v [i].x = pk2(t.x, t.y); sh_v [i].y = pk2(t.z, t.w);
    }
    __syncthreads();

    int cs = *covset;
    float* eo = img ? g_e_img : g_e;
    const float4* Fr = (const float4*)(F + ((size_t)b * Lr + l0) * A_);

    ull c2a = cs ? cst2(cov[b * Lr + l0])     : 0ULL;
    ull c2b = cs ? cst2(cov[b * Lr + l0 + 1]) : 0ULL;

    // double-buffered chunk loads for both rows
    float4 cura = __ldcs(&Fr[lane]);
    float4 curb = __ldcs(&Fr[256 + lane]);

    ull acc0a = 0ULL, acc1a = 0ULL, acc0b = 0ULL, acc1b = 0ULL;
#pragma unroll
    for (int ch = 0; ch < 8; ch++) {
        float4 nxta, nxtb;
        if (ch < 7) {
            nxta = __ldcs(&Fr[(ch + 1) * 32 + lane]);
            nxtb = __ldcs(&Fr[256 + (ch + 1) * 32 + lane]);
        }
        int j = ch * 32 + lane;
        ulonglong2 d = sh_df[j], w = sh_wc[j], vv = sh_v[j];

        ull xa0 = clamp2(add2(pk2(cura.x, cura.y), fma2(c2a, w.x, d.x)));
        ull xa1 = clamp2(add2(pk2(cura.z, cura.w), fma2(c2a, w.y, d.y)));
        ull xb0 = clamp2(add2(pk2(curb.x, curb.y), fma2(c2b, w.x, d.x)));
        ull xb1 = clamp2(add2(pk2(curb.z, curb.w), fma2(c2b, w.y, d.y)));
        acc0a = fma2(vv.x, tanh2(xa0), acc0a);
        acc1a = fma2(vv.y, tanh2(xa1), acc1a);
        acc0b = fma2(vv.x, tanh2(xb0), acc0b);
        acc1b = fma2(vv.y, tanh2(xb1), acc1b);

        cura = nxta; curb = nxtb;
    }

    ull acca = add2(acc0a, acc1a);
    ull accb = add2(acc0b, acc1b);
    float sa0, sa1, sb0, sb1;
    upk2(acca, sa0, sa1); upk2(accb, sb0, sb1);
    float sa = sa0 + sa1, sb = sb0 + sb1;
#pragma unroll
    for (int o = 16; o > 0; o >>= 1) {
        sa += __shfl_xor_sync(0xffffffffu, sa, o);
        sb += __shfl_xor_sync(0xffffffffu, sb, o);
    }
    if (lane == 0) {
        eo[b * Lr + l0]     = sa;
        eo[b * Lr + l0 + 1] = sb;
    }
}

// ---------------- softmax (+mask renorm for text) + coverage update --------
__global__ __launch_bounds__(256) void softmax_kernel(
    const float* __restrict__ mask, const float* __restrict__ cov,
    const int* __restrict__ covset, float* __restrict__ attn_out,
    float* __restrict__ cov_out, int Lr, int img)
{
    int b = blockIdx.x, tid = threadIdx.x;
    int n = Lr >> 8;                       // 4 text, 1 img
    const float* e = img ? g_e_img : g_e;
    float* attn_g  = img ? g_attn_img : g_attn;
    __shared__ float red[256];

    const float* er = e + b * Lr;
    float vals[4], ex[4], p[4];
    float m = -3.4e38f;
    for (int i = 0; i < n; i++) { vals[i] = er[tid + (i << 8)]; m = fmaxf(m, vals[i]); }
    red[tid] = m; __syncthreads();
    for (int s = 128; s > 0; s >>= 1) { if (tid < s) red[tid] = fmaxf(red[tid], red[tid + s]); __syncthreads(); }
    m = red[0]; __syncthreads();

    float sum = 0.0f;
    for (int i = 0; i < n; i++) { ex[i] = __expf(vals[i] - m); sum += ex[i]; }
    red[tid] = sum; __syncthreads();
    for (int s = 128; s > 0; s >>= 1) { if (tid < s) red[tid] += red[tid + s]; __syncthreads(); }
    float S = red[0]; __syncthreads();

    float sum2 = 0.0f;
    for (int i = 0; i < n; i++) {
        float mk = mask ? mask[b * Lr + tid + (i << 8)] : 1.0f;
        p[i] = ex[i] / S * mk; sum2 += p[i];
    }
    red[tid] = sum2; __syncthreads();
    for (int s = 128; s > 0; s >>= 1) { if (tid < s) red[tid] += red[tid + s]; __syncthreads(); }
    float S2 = red[0];

    int cs = *covset;
    for (int i = 0; i < n; i++) {
        int idx = b * Lr + tid + (i << 8);
        float at = p[i] / S2;
        attn_g[idx]  = at;
        attn_out[idx] = at;
        cov_out[idx] = cs ? (cov[idx] + at) : at;
    }
}

// ---------------- ctx = attn · enc_outputs (split-L, 32 rows/chunk) --------
// rolling depth-8 prefetch; __ldcs streaming loads; dual accumulator chains
__global__ __launch_bounds__(256, 4) void ctx_partial(
    const float* __restrict__ O, int Lr, int img)
{
    int b = blockIdx.x, ch = blockIdx.y;
    const float* attn = img ? g_attn_img : g_attn;
    float* part       = img ? g_ctxp_i   : g_ctxp_t;
    __shared__ float ash[32];
    int tid = threadIdx.x;
    if (tid < 32) ash[tid] = attn[b * Lr + ch * 32 + tid];
    __syncthreads();

    const float4* Ob = (const float4*)(O + ((size_t)b * Lr + (size_t)ch * 32) * A_);

    float4 buf[8];
#pragma unroll
    for (int i = 0; i < 8; i++) buf[i] = __ldcs(&Ob[(size_t)i * 256 + tid]);

    float4 acc0 = make_float4(0.f, 0.f, 0.f, 0.f);
    float4 acc1 = make_float4(0.f, 0.f, 0.f, 0.f);
#pragma unroll
    for (int l = 0; l < 32; l++) {
        float4 o = buf[l & 7];
        if (l < 24) buf[l & 7] = __ldcs(&Ob[(size_t)(l + 8) * 256 + tid]);
        float s = ash[l];
        if (l & 1) {
            acc1.x += s * o.x; acc1.y += s * o.y; acc1.z += s * o.z; acc1.w += s * o.w;
        } else {
            acc0.x += s * o.x; acc0.y += s * o.y; acc0.z += s * o.z; acc0.w += s * o.w;
        }
    }
    acc0.x += acc1.x; acc0.y += acc1.y; acc0.z += acc1.z; acc0.w += acc1.w;
    float4* pp = (float4*)(part + ((size_t)b * gridDim.y + ch) * A_);
    pp[tid] = acc0;
}

__global__ __launch_bounds__(256) void ctx_reduce(int CH, int img)
{
    int idx = blockIdx.x * 256 + threadIdx.x;   // 0..65535
    int b = idx >> 10, a = idx & 1023;
    const float* part = img ? g_ctxp_i : g_ctxp_t;
    float s = 0.0f;
    for (int c = 0; c < CH; c++) s += part[((size_t)b * CH + c) * 1024 + a];
    (img ? g_ctx_i : g_ctx_t)[idx] = s;
}

// ---------------- final: beta gating + ctx_mm -------------------------------
__global__ __launch_bounds__(256) void final_kernel(
    const float* __restrict__ v3, const float* __restrict__ v4,
    float* __restrict__ out)
{
    int idx = blockIdx.x * 256 + threadIdx.x;   // 0..65535
    int a = idx & 1023;
    float ca = g_df[2 * 65536 + idx];           // dec@W3 + b3
    float cb = g_df[3 * 65536 + idx];           // dec@W4 + b4
#pragma unroll
    for (int c = 0; c < 8; c++) {
        ca += g_gp2[(c << 16) + idx];           // + ctx_t @ WA
        cb += g_gp2[((8 + c) << 16) + idx];     // + ctx_i @ WB
    }
    float b1v = v3[a] * tanhf(ca);
    float b2v = v4[a] * tanhf(cb);
    out[idx] = b1v * g_ctx_t[idx] + b2v * g_ctx_i[idx];
}

// ---------------- launch ----------------------------------------------------
extern "C" void kernel_launch(void* const* d_in, const int* in_sizes, int n_in,
                              void* d_out, int out_size)
{
    const float* h0       = (const float*)d_in[0];
    const float* h1       = (const float*)d_in[1];
    const float* enc_out  = (const float*)d_in[2];
    const float* enc_feat = (const float*)d_in[3];
    const float* enc_mask = (const float*)d_in[4];
    const float* coverage = (const float*)d_in[5];
    const float* eio      = (const float*)d_in[6];
    const float* eif      = (const float*)d_in[7];
    const float* cov_img  = (const float*)d_in[9];
    const int*   covset   = (const int*)  d_in[10];
    const float* W1 = (const float*)d_in[11];
    const float* b1 = (const float*)d_in[12];
    const float* W2 = (const float*)d_in[13];
    const float* b2 = (const float*)d_in[14];
    const float* W3 = (const float*)d_in[15];
    const float* b3 = (const float*)d_in[16];
    const float* W4 = (const float*)d_in[17];
    const float* b4 = (const float*)d_in[18];
    const float* WA = (const float*)d_in[19];
    const float* WB = (const float*)d_in[20];
    const float* v1 = (const float*)d_in[21];
    const float* v2 = (const float*)d_in[22];
    const float* v3 = (const float*)d_in[23];
    const float* v4 = (const float*)d_in[24];
    const float* wc = (const float*)d_in[25];
    const float* wci= (const float*)d_in[26];

    float* out = (float*)d_out;
    // output layout: ctx_mm[65536] | attn[65536] | attn_img[16384] |
    //                coverage[65536] | coverage_img[16384]
    float* o_attn     = out + 65536;
    float* o_attn_img = out + 131072;
    float* o_cov      = out + 147456;
    float* o_cov_img  = out + 212992;

    // 1) dec@{W1..W4}+bias  (split-K)
    gemm_partial<<<dim3(4, 8, 4), 256>>>(h0, h1, W1, W2, W3, W4, 0);
    gemm_reduce<<<1024, 256>>>(b1, b2, b3, b4);

    // 2) attention energies (big HBM passes; 16 rows/block, 2 rows/warp)
    energy_kernel<<<(B_ * L_)  / 16, 256>>>(enc_feat, coverage, v1, wc,  covset, 0, L_,  0);
    energy_kernel<<<(B_ * LI_) / 16, 256>>>(eif,      cov_img,  v2, wci, covset, 1, LI_, 1);

    // 3) softmax + mask-renorm (text) / softmax (img) + coverage update
    softmax_kernel<<<B_, 256>>>(enc_mask, coverage, covset, o_attn,     o_cov,     L_,  0);
    softmax_kernel<<<B_, 256>>>(nullptr,  cov_img,  covset, o_attn_img, o_cov_img, LI_, 1);

    // 4) contexts (big HBM passes, split-L 32 rows/chunk)
    ctx_partial<<<dim3(B_, 32), 256>>>(enc_out, L_,  0);
    ctx_partial<<<dim3(B_, 8),  256>>>(eio,     LI_, 1);
    ctx_reduce<<<256, 256>>>(32, 0);
    ctx_reduce<<<256, 256>>>(8,  1);

    // 5) ctx@{WA,WB} (split-K) + gated combine
    gemm_partial<<<dim3(4, 8, 2), 256>>>(nullptr, nullptr, WA, WB, WA, WB, 1);
    final_kernel<<<256, 256>>>(v3, v4, out);
}

// round 11
// speedup vs baseline: 1.1052x; 1.0711x over previous
#include <cuda_runtime.h>
#include <cstdint>

typedef unsigned long long ull;

#define B_  64
#define L_  1024
#define LI_ 256
#define A_  1024
#define H_  512

// ---------------- scratch (static device globals; no allocations) ----------
__device__ float g_gp1[4*8*B_*A_];      // gemm1 split-k partials [mat][kc][b][a]
__device__ float g_gp2[2*8*B_*A_];      // gemm2 split-k partials
__device__ float g_df [4*B_*A_];        // df, dfi, d3, d4
__device__ float g_e      [B_*L_];
__device__ float g_e_img  [B_*LI_];
__device__ float g_attn   [B_*L_];
__device__ float g_attn_img[B_*LI_];
__device__ float g_ctxp_t[B_*32*A_];    // ctx split-L partials (32 chunks)
__device__ float g_ctxp_i[B_*8*A_];     // (8 chunks)
__device__ float g_ctx_t[B_*A_];
__device__ float g_ctx_i[B_*A_];

// ---------------- packed f32x2 helpers -------------------------------------
__device__ __forceinline__ ull pk2(float lo, float hi) {
    ull d; asm("mov.b64 %0,{%1,%2};" : "=l"(d) : "f"(lo), "f"(hi)); return d;
}
__device__ __forceinline__ void upk2(ull d, float& lo, float& hi) {
    asm("mov.b64 {%0,%1},%2;" : "=f"(lo), "=f"(hi) : "l"(d));
}
__device__ __forceinline__ ull mul2(ull a, ull b) {
    ull d; asm("mul.rn.f32x2 %0,%1,%2;" : "=l"(d) : "l"(a), "l"(b)); return d;
}
__device__ __forceinline__ ull add2(ull a, ull b) {
    ull d; asm("add.rn.f32x2 %0,%1,%2;" : "=l"(d) : "l"(a), "l"(b)); return d;
}
__device__ __forceinline__ ull fma2(ull a, ull b, ull c) {
    ull d; asm("fma.rn.f32x2 %0,%1,%2,%3;" : "=l"(d) : "l"(a), "l"(b), "l"(c)); return d;
}
__device__ __forceinline__ ull cst2(float c) { return pk2(c, c); }

// clamp both halves to [-4.9, 4.9] via FMNMX (alu pipe, not fma pipe)
__device__ __forceinline__ ull clamp2(ull x) {
    float lo, hi; upk2(x, lo, hi);
    lo = fminf(fmaxf(lo, -4.9f), 4.9f);
    hi = fminf(fmaxf(hi, -4.9f), 4.9f);
    return pk2(lo, hi);
}

// FMA-only packed tanh: order-7 Lambert continued fraction, valid on [-4.9,4.9]
// (inputs must be pre-clamped). Max abs err ~8.5e-5. 13 f32x2 ops.
__device__ __forceinline__ ull tanh2(ull x) {
    ull x2 = mul2(x, x);
    ull p = fma2(x2, cst2(7.4000296e-6f), cst2(2.7972028e-3f));
    p = fma2(x2, p, cst2(0.12820513f));
    p = fma2(x2, p, cst2(1.0f));
    p = mul2(p, x);
    ull q = fma2(x2, cst2(2.0718275e-4f), cst2(0.023310023f));
    q = fma2(x2, q, cst2(0.46153846f));
    q = fma2(x2, q, cst2(1.0f));
    // reciprocal of q (q >= 1, positive): bit-hack + 2 Newton, no MUFU
    float ql, qh; upk2(q, ql, qh);
    float rl = __uint_as_float(0x7EF311C3u - __float_as_uint(ql));
    float rh = __uint_as_float(0x7EF311C3u - __float_as_uint(qh));
    ull r = pk2(rl, rh);
    ull nq = q ^ 0x8000000080000000ULL;
    ull two = cst2(2.0f);
    r = mul2(r, fma2(nq, r, two));
    r = mul2(r, fma2(nq, r, two));
    return mul2(p, r);
}

// ---------------- GEMM: split-K partial sums, f32x2 accumulators ----------
__global__ __launch_bounds__(256) void gemm_partial(
    const float* __restrict__ sa, const float* __restrict__ sb,
    const float* __restrict__ W0, const float* __restrict__ W1p,
    const float* __restrict__ W2p, const float* __restrict__ W3p,
    int mode)
{
    int z = blockIdx.z, kc = blockIdx.y;
    const float* W = (z == 0) ? W0 : (z == 1) ? W1p : (z == 2) ? W2p : W3p;

    __shared__ ulonglong2 dsh2[128 * 16];     // [k][bpair/2], 16B aligned
    ull* dsh = (ull*)dsh2;
    int tid = threadIdx.x;

    for (int i = tid; i < 128 * 32; i += 256) {
        int k = i >> 5, bp = i & 31;
        int kg = kc * 128 + k;
        int b0 = bp * 2, b1 = b0 + 1;
        float f0, f1;
        if (mode) {
            const float* s = z ? g_ctx_i : g_ctx_t;
            f0 = s[b0 * 1024 + kg];
            f1 = s[b1 * 1024 + kg];
        } else {
            if (kg < 512) { f0 = sa[b0 * 512 + kg];       f1 = sa[b1 * 512 + kg]; }
            else          { f0 = sb[b0 * 512 + kg - 512]; f1 = sb[b1 * 512 + kg - 512]; }
        }
        dsh[i] = pk2(f0, f1);
    }
    __syncthreads();

    int a = blockIdx.x * 256 + tid;
    const float* Wc = W + (size_t)(kc * 128) * 1024 + a;

    ull acc[32];
#pragma unroll
    for (int i = 0; i < 32; i++) acc[i] = 0ULL;

    for (int k = 0; k < 128; k++) {
        float w = __ldcs(&Wc[(size_t)k * 1024]);
        ull w2 = pk2(w, w);
        const ulonglong2* dk = &dsh2[k * 16];
#pragma unroll
        for (int q = 0; q < 16; q++) {
            ulonglong2 d = dk[q];
            acc[2 * q]     = fma2(d.x, w2, acc[2 * q]);
            acc[2 * q + 1] = fma2(d.y, w2, acc[2 * q + 1]);
        }
    }

    float* gp = mode ? g_gp2 : g_gp1;
    float* op = gp + ((size_t)(z * 8 + kc) * 64) * 1024 + a;
#pragma unroll
    for (int bp = 0; bp < 32; bp++) {
        float lo, hi; upk2(acc[bp], lo, hi);
        op[(size_t)(2 * bp)     * 1024] = lo;
        op[(size_t)(2 * bp + 1) * 1024] = hi;
    }
}

// reduce gemm1 partials + bias -> g_df[mat][b][a]
__global__ __launch_bounds__(256) void gemm_reduce(
    const float* __restrict__ bias0, const float* __restrict__ bias1,
    const float* __restrict__ bias2, const float* __restrict__ bias3)
{
    int idx = blockIdx.x * 256 + threadIdx.x;    // 0..262143
    int mat = idx >> 16;
    int r   = idx & 65535;
    int a   = idx & 1023;
    const float* bias = (mat == 0) ? bias0 : (mat == 1) ? bias1 : (mat == 2) ? bias2 : bias3;
    float s = bias[a];
#pragma unroll
    for (int c = 0; c < 8; c++) s += g_gp1[((mat * 8 + c) << 16) + r];
    g_df[idx] = s;
}

// ---------------- energy: e[b,l] = sum_a v[a]*tanh(F[b,l,a]+df[b,a]+cov*wc[a])
// chunk-outer / row-inner: one warp per 2 rows. Per chunk: 1x LDS of d/w/v
// (row-invariant), double-buffered LDGs, 4 independent tanh chains (ILP=4).
__global__ __launch_bounds__(256, 4) void energy_kernel(
    const float* __restrict__ F, const float* __restrict__ cov,
    const float* __restrict__ v, const float* __restrict__ wcp,
    const int* __restrict__ covset, int mat, int Lr, int img)
{
    __shared__ ulonglong2 sh_df[256], sh_wc[256], sh_v[256];
    int rgpb = Lr >> 4;                        // 16-row groups per batch
    int b  = blockIdx.x / rgpb;
    int l0 = (blockIdx.x % rgpb) * 16 + (threadIdx.x >> 5) * 2;
    int lane = threadIdx.x & 31;

    const float* dfm = g_df + (size_t)mat * (B_ * A_) + (size_t)b * A_;
    const float4* dfr = (const float4*)dfm;
    const float4* wcr = (const float4*)wcp;
    const float4* vr  = (const float4*)v;
    {
        int i = threadIdx.x;
        float4 t = dfr[i]; sh_df[i].x = pk2(t.x, t.y); sh_df[i].y = pk2(t.z, t.w);
        t = wcr[i];        sh_wc[i].x = pk2(t.x, t.y); sh_wc[i].y = pk2(t.z, t.w);
        t = vr[i];         sh_v [i].x = pk2(t.x, t.y); sh_v [i].y = pk2(t.z, t.w);
    }
    __syncthreads();

    int cs = *covset;
    float* eo = img ? g_e_img : g_e;
    const float4* Fr = (const float4*)(F + ((size_t)b * Lr + l0) * A_);

    ull c2a = cs ? cst2(cov[b * Lr + l0])     : 0ULL;
    ull c2b = cs ? cst2(cov[b * Lr + l0 + 1]) : 0ULL;

    // double-buffered chunk loads for both rows
    float4 cura = __ldcs(&Fr[lane]);
    float4 curb = __ldcs(&Fr[256 + lane]);

    ull acc0a = 0ULL, acc1a = 0ULL, acc0b = 0ULL, acc1b = 0ULL;
#pragma unroll
    for (int ch = 0; ch < 8; ch++) {
        float4 nxta, nxtb;
        if (ch < 7) {
            nxta = __ldcs(&Fr[(ch + 1) * 32 + lane]);
            nxtb = __ldcs(&Fr[256 + (ch + 1) * 32 + lane]);
        }
        int j = ch * 32 + lane;
        ulonglong2 d = sh_df[j], w = sh_wc[j], vv = sh_v[j];

        ull xa0 = clamp2(add2(pk2(cura.x, cura.y), fma2(c2a, w.x, d.x)));
        ull xa1 = clamp2(add2(pk2(cura.z, cura.w), fma2(c2a, w.y, d.y)));
        ull xb0 = clamp2(add2(pk2(curb.x, curb.y), fma2(c2b, w.x, d.x)));
        ull xb1 = clamp2(add2(pk2(curb.z, curb.w), fma2(c2b, w.y, d.y)));
        acc0a = fma2(vv.x, tanh2(xa0), acc0a);
        acc1a = fma2(vv.y, tanh2(xa1), acc1a);
        acc0b = fma2(vv.x, tanh2(xb0), acc0b);
        acc1b = fma2(vv.y, tanh2(xb1), acc1b);

        cura = nxta; curb = nxtb;
    }

    ull acca = add2(acc0a, acc1a);
    ull accb = add2(acc0b, acc1b);
    float sa0, sa1, sb0, sb1;
    upk2(acca, sa0, sa1); upk2(accb, sb0, sb1);
    float sa = sa0 + sa1, sb = sb0 + sb1;
#pragma unroll
    for (int o = 16; o > 0; o >>= 1) {
        sa += __shfl_xor_sync(0xffffffffu, sa, o);
        sb += __shfl_xor_sync(0xffffffffu, sb, o);
    }
    if (lane == 0) {
        eo[b * Lr + l0]     = sa;
        eo[b * Lr + l0 + 1] = sb;
    }
}

// ---------------- softmax (+mask renorm for text) + coverage update --------
__global__ __launch_bounds__(256) void softmax_kernel(
    const float* __restrict__ mask, const float* __restrict__ cov,
    const int* __restrict__ covset, float* __restrict__ attn_out,
    float* __restrict__ cov_out, int Lr, int img)
{
    int b = blockIdx.x, tid = threadIdx.x;
    int n = Lr >> 8;                       // 4 text, 1 img
    const float* e = img ? g_e_img : g_e;
    float* attn_g  = img ? g_attn_img : g_attn;
    __shared__ float red[256];

    const float* er = e + b * Lr;
    float vals[4], ex[4], p[4];
    float m = -3.4e38f;
    for (int i = 0; i < n; i++) { vals[i] = er[tid + (i << 8)]; m = fmaxf(m, vals[i]); }
    red[tid] = m; __syncthreads();
    for (int s = 128; s > 0; s >>= 1) { if (tid < s) red[tid] = fmaxf(red[tid], red[tid + s]); __syncthreads(); }
    m = red[0]; __syncthreads();

    float sum = 0.0f;
    for (int i = 0; i < n; i++) { ex[i] = __expf(vals[i] - m); sum += ex[i]; }
    red[tid] = sum; __syncthreads();
    for (int s = 128; s > 0; s >>= 1) { if (tid < s) red[tid] += red[tid + s]; __syncthreads(); }
    float S = red[0]; __syncthreads();

    float sum2 = 0.0f;
    for (int i = 0; i < n; i++) {
        float mk = mask ? mask[b * Lr + tid + (i << 8)] : 1.0f;
        p[i] = ex[i] / S * mk; sum2 += p[i];
    }
    red[tid] = sum2; __syncthreads();
    for (int s = 128; s > 0; s >>= 1) { if (tid < s) red[tid] += red[tid + s]; __syncthreads(); }
    float S2 = red[0];

    int cs = *covset;
    for (int i = 0; i < n; i++) {
        int idx = b * Lr + tid + (i << 8);
        float at = p[i] / S2;
        attn_g[idx]  = at;
        attn_out[idx] = at;
        cov_out[idx] = cs ? (cov[idx] + at) : at;
    }
}

// ---------------- ctx = attn · enc_outputs (split-L, 32 rows/chunk) --------
// rolling depth-8 prefetch; __ldcs streaming loads; dual accumulator chains
__global__ __launch_bounds__(256, 4) void ctx_partial(
    const float* __restrict__ O, int Lr, int img)
{
    int b = blockIdx.x, ch = blockIdx.y;
    const float* attn = img ? g_attn_img : g_attn;
    float* part       = img ? g_ctxp_i   : g_ctxp_t;
    __shared__ float ash[32];
    int tid = threadIdx.x;
    if (tid < 32) ash[tid] = attn[b * Lr + ch * 32 + tid];
    __syncthreads();

    const float4* Ob = (const float4*)(O + ((size_t)b * Lr + (size_t)ch * 32) * A_);

    float4 buf[8];
#pragma unroll
    for (int i = 0; i < 8; i++) buf[i] = __ldcs(&Ob[(size_t)i * 256 + tid]);

    float4 acc0 = make_float4(0.f, 0.f, 0.f, 0.f);
    float4 acc1 = make_float4(0.f, 0.f, 0.f, 0.f);
#pragma unroll
    for (int l = 0; l < 32; l++) {
        float4 o = buf[l & 7];
        if (l < 24) buf[l & 7] = __ldcs(&Ob[(size_t)(l + 8) * 256 + tid]);
        float s = ash[l];
        if (l & 1) {
            acc1.x += s * o.x; acc1.y += s * o.y; acc1.z += s * o.z; acc1.w += s * o.w;
        } else {
            acc0.x += s * o.x; acc0.y += s * o.y; acc0.z += s * o.z; acc0.w += s * o.w;
        }
    }
    acc0.x += acc1.x; acc0.y += acc1.y; acc0.z += acc1.z; acc0.w += acc1.w;
    float4* pp = (float4*)(part + ((size_t)b * gridDim.y + ch) * A_);
    pp[tid] = acc0;
}

__global__ __launch_bounds__(256) void ctx_reduce(int CH, int img)
{
    int idx = blockIdx.x * 256 + threadIdx.x;   // 0..65535
    int b = idx >> 10, a = idx & 1023;
    const float* part = img ? g_ctxp_i : g_ctxp_t;
    float s = 0.0f;
    for (int c = 0; c < CH; c++) s += part[((size_t)b * CH + c) * 1024 + a];
    (img ? g_ctx_i : g_ctx_t)[idx] = s;
}

// ---------------- final: beta gating + ctx_mm -------------------------------
__global__ __launch_bounds__(256) void final_kernel(
    const float* __restrict__ v3, const float* __restrict__ v4,
    float* __restrict__ out)
{
    int idx = blockIdx.x * 256 + threadIdx.x;   // 0..65535
    int a = idx & 1023;
    float ca = g_df[2 * 65536 + idx];           // dec@W3 + b3
    float cb = g_df[3 * 65536 + idx];           // dec@W4 + b4
#pragma unroll
    for (int c = 0; c < 8; c++) {
        ca += g_gp2[(c << 16) + idx];           // + ctx_t @ WA
        cb += g_gp2[((8 + c) << 16) + idx];     // + ctx_i @ WB
    }
    float b1v = v3[a] * tanhf(ca);
    float b2v = v4[a] * tanhf(cb);
    out[idx] = b1v * g_ctx_t[idx] + b2v * g_ctx_i[idx];
}

// ---------------- launch: fork img chain onto a side stream ------------------
extern "C" void kernel_launch(void* const* d_in, const int* in_sizes, int n_in,
                              void* d_out, int out_size)
{
    const float* h0       = (const float*)d_in[0];
    const float* h1       = (const float*)d_in[1];
    const float* enc_out  = (const float*)d_in[2];
    const float* enc_feat = (const float*)d_in[3];
    const float* enc_mask = (const float*)d_in[4];
    const float* coverage = (const float*)d_in[5];
    const float* eio      = (const float*)d_in[6];
    const float* eif      = (const float*)d_in[7];
    const float* cov_img  = (const float*)d_in[9];
    const int*   covset   = (const int*)  d_in[10];
    const float* W1 = (const float*)d_in[11];
    const float* b1 = (const float*)d_in[12];
    const float* W2 = (const float*)d_in[13];
    const float* b2 = (const float*)d_in[14];
    const float* W3 = (const float*)d_in[15];
    const float* b3 = (const float*)d_in[16];
    const float* W4 = (const float*)d_in[17];
    const float* b4 = (const float*)d_in[18];
    const float* WA = (const float*)d_in[19];
    const float* WB = (const float*)d_in[20];
    const float* v1 = (const float*)d_in[21];
    const float* v2 = (const float*)d_in[22];
    const float* v3 = (const float*)d_in[23];
    const float* v4 = (const float*)d_in[24];
    const float* wc = (const float*)d_in[25];
    const float* wci= (const float*)d_in[26];

    float* out = (float*)d_out;
    // output layout: ctx_mm[65536] | attn[65536] | attn_img[16384] |
    //                coverage[65536] | coverage_img[16384]
    float* o_attn     = out + 65536;
    float* o_attn_img = out + 131072;
    float* o_cov      = out + 147456;
    float* o_cov_img  = out + 212992;

    // one-time side stream + fork/join events (DisableTiming: capture-legal)
    static cudaStream_t s_img = nullptr;
    static cudaEvent_t  ev_fork = nullptr, ev_join = nullptr;
    if (!s_img) {
        cudaStreamCreateWithFlags(&s_img, cudaStreamNonBlocking);
        cudaEventCreateWithFlags(&ev_fork, cudaEventDisableTiming);
        cudaEventCreateWithFlags(&ev_join, cudaEventDisableTiming);
    }

    // 1) dec@{W1..W4}+bias  (split-K) — on main (captured) stream
    gemm_partial<<<dim3(4, 8, 4), 256>>>(h0, h1, W1, W2, W3, W4, 0);
    gemm_reduce<<<1024, 256>>>(b1, b2, b3, b4);

    // fork: img chain depends on gemm_reduce
    cudaEventRecord(ev_fork, 0);
    cudaStreamWaitEvent(s_img, ev_fork, 0);

    // ---- img chain on side stream (fully hidden under text chain) ----
    energy_kernel<<<(B_ * LI_) / 16, 256, 0, s_img>>>(eif, cov_img, v2, wci, covset, 1, LI_, 1);
    softmax_kernel<<<B_, 256, 0, s_img>>>(nullptr, cov_img, covset, o_attn_img, o_cov_img, LI_, 1);
    ctx_partial<<<dim3(B_, 8), 256, 0, s_img>>>(eio, LI_, 1);
    ctx_reduce<<<256, 256, 0, s_img>>>(8, 1);
    cudaEventRecord(ev_join, s_img);

    // ---- text chain on main stream ----
    energy_kernel<<<(B_ * L_) / 16, 256>>>(enc_feat, coverage, v1, wc, covset, 0, L_, 0);
    softmax_kernel<<<B_, 256>>>(enc_mask, coverage, covset, o_attn, o_cov, L_, 0);
    ctx_partial<<<dim3(B_, 32), 256>>>(enc_out, L_, 0);
    ctx_reduce<<<256, 256>>>(32, 0);

    // join: gemm2 needs both ctx_t and ctx_i
    cudaStreamWaitEvent(0, ev_join, 0);

    // 5) ctx@{WA,WB} (split-K) + gated combine
    gemm_partial<<<dim3(4, 8, 2), 256>>>(nullptr, nullptr, WA, WB, WA, WB, 1);
    final_kernel<<<256, 256>>>(v3, v4, out);
}